// round 1
// baseline (speedup 1.0000x reference)
#include <cuda_runtime.h>
#include <math.h>

// Problem constants
#define Lc   8
#define Bc   4
#define Sc   2048
#define Dc   256
#define SDc  512
#define Mc   (Bc*Sc)   // 8192 rows

// ---------------- scratch (device globals; no allocation allowed) -------------
__device__ float g_h   [(size_t)Mc*Dc*2];    // current activation, interleaved [M,D,2]
__device__ float g_xn  [(size_t)Mc*2*Dc];    // LN output, planes [M, 2D] (== gate_in)
__device__ float g_Bx  [(size_t)Mc*2*SDc];   // B projection, planes [M, 2SD]
__device__ float g_gt  [(size_t)Mc*SDc];     // gates [M, SD]
__device__ float g_hall[(size_t)Mc*2*SDc];   // scan output, planes [M, 2SD]
__device__ float g_Dx  [(size_t)Mc*2*Dc];    // D projection, planes [M, 2D]

// ---------------- LayerNorm over D, separate real/imag stats ------------------
// src: interleaved [M, D, 2]. If dstPlanes != null write planes [M,2D], else
// write interleaved [M,D,2] to dstInter (final LN).
__global__ void ln_kernel(const float* __restrict__ src,
                          const float* __restrict__ gw,
                          const float* __restrict__ bw,
                          float* __restrict__ dstPlanes,
                          float* __restrict__ dstInter)
{
    int m = blockIdx.x;
    int d = threadIdx.x;            // 0..255
    const float* row = src + (size_t)m * Dc * 2;
    float hr = row[2*d], hi = row[2*d+1];

    float v0 = hr, v1 = hi, v2 = hr*hr, v3 = hi*hi;
    #pragma unroll
    for (int o = 16; o > 0; o >>= 1) {
        v0 += __shfl_down_sync(0xffffffffu, v0, o);
        v1 += __shfl_down_sync(0xffffffffu, v1, o);
        v2 += __shfl_down_sync(0xffffffffu, v2, o);
        v3 += __shfl_down_sync(0xffffffffu, v3, o);
    }
    __shared__ float sm[4][8];
    __shared__ float stats[4];
    int w = d >> 5, ln = d & 31;
    if (ln == 0) { sm[0][w]=v0; sm[1][w]=v1; sm[2][w]=v2; sm[3][w]=v3; }
    __syncthreads();
    if (d == 0) {
        float s0=0,s1=0,s2=0,s3=0;
        #pragma unroll
        for (int i=0;i<8;i++){ s0+=sm[0][i]; s1+=sm[1][i]; s2+=sm[2][i]; s3+=sm[3][i]; }
        float inv = 1.0f / (float)Dc;
        float mur = s0*inv, mui = s1*inv;
        stats[0]=mur; stats[1]=rsqrtf(s2*inv - mur*mur + 1e-5f);
        stats[2]=mui; stats[3]=rsqrtf(s3*inv - mui*mui + 1e-5f);
    }
    __syncthreads();
    float nr = (hr - stats[0]) * stats[1] * gw[d] + bw[d];
    float ni = (hi - stats[2]) * stats[3] * gw[d] + bw[d];
    if (dstPlanes) {
        dstPlanes[(size_t)m*2*Dc + d]      = nr;
        dstPlanes[(size_t)m*2*Dc + Dc + d] = ni;
    } else {
        float* o = dstInter + (size_t)m*Dc*2;
        o[2*d]   = nr;
        o[2*d+1] = ni;
    }
}

// ---------------- complex GEMM: A planes [M, lda=2K] x (Wr,Wi)[K,N] -----------
// mode A (hOut==null): write planes outP [M, 2N]
// mode B (hOut!=null): y = acc + Dx; out = yr*y + y; hOut = resid + 0.1*out
//                      (interleaved [M,N,2])
__global__ void __launch_bounds__(256, 2)
cgemm_kernel(const float* __restrict__ A, int lda,
             const float* __restrict__ Wr, const float* __restrict__ Wi,
             int K, int N,
             float* __restrict__ outP,
             const float* __restrict__ DxP,
             const float* __restrict__ resid,
             float* __restrict__ hOut)
{
    __shared__ float Ar[16][64], Ai[16][64], Brs[16][64], Bis[16][64];
    int tid = threadIdx.x;
    int m0 = blockIdx.y * 64, n0 = blockIdx.x * 64;
    int arow = tid >> 2,  ac = (tid & 3) * 4;   // A: 64 rows x 16 k, float4 per plane
    int brow = tid >> 4,  bc = (tid & 15) * 4;  // W: 16 k x 64 n, float4 per plane
    int ty = tid >> 4,    tx = tid & 15;

    float cr[4][4] = {}, ci[4][4] = {};

    for (int k0 = 0; k0 < K; k0 += 16) {
        float4 va = *(const float4*)(A + (size_t)(m0+arow)*lda + k0 + ac);
        float4 vb = *(const float4*)(A + (size_t)(m0+arow)*lda + K + k0 + ac);
        Ar[ac+0][arow]=va.x; Ar[ac+1][arow]=va.y; Ar[ac+2][arow]=va.z; Ar[ac+3][arow]=va.w;
        Ai[ac+0][arow]=vb.x; Ai[ac+1][arow]=vb.y; Ai[ac+2][arow]=vb.z; Ai[ac+3][arow]=vb.w;
        *(float4*)&Brs[brow][bc] = *(const float4*)(Wr + (size_t)(k0+brow)*N + n0 + bc);
        *(float4*)&Bis[brow][bc] = *(const float4*)(Wi + (size_t)(k0+brow)*N + n0 + bc);
        __syncthreads();
        #pragma unroll
        for (int kk = 0; kk < 16; kk++) {
            float4 a4r = *(float4*)&Ar [kk][ty*4];
            float4 a4i = *(float4*)&Ai [kk][ty*4];
            float4 b4r = *(float4*)&Brs[kk][tx*4];
            float4 b4i = *(float4*)&Bis[kk][tx*4];
            float arr[4]={a4r.x,a4r.y,a4r.z,a4r.w};
            float aii[4]={a4i.x,a4i.y,a4i.z,a4i.w};
            float brr[4]={b4r.x,b4r.y,b4r.z,b4r.w};
            float bii[4]={b4i.x,b4i.y,b4i.z,b4i.w};
            #pragma unroll
            for (int i=0;i<4;i++)
                #pragma unroll
                for (int j=0;j<4;j++) {
                    cr[i][j] = fmaf(arr[i], brr[j], cr[i][j]);
                    cr[i][j] = fmaf(-aii[i], bii[j], cr[i][j]);
                    ci[i][j] = fmaf(arr[i], bii[j], ci[i][j]);
                    ci[i][j] = fmaf(aii[i], brr[j], ci[i][j]);
                }
        }
        __syncthreads();
    }

    if (hOut == nullptr) {
        #pragma unroll
        for (int i=0;i<4;i++) {
            int row = m0 + ty*4 + i;
            #pragma unroll
            for (int j=0;j<4;j++) {
                int col = n0 + tx*4 + j;
                outP[(size_t)row*2*N + col]     = cr[i][j];
                outP[(size_t)row*2*N + N + col] = ci[i][j];
            }
        }
    } else {
        #pragma unroll
        for (int i=0;i<4;i++) {
            int row = m0 + ty*4 + i;
            #pragma unroll
            for (int j=0;j<4;j++) {
                int col = n0 + tx*4 + j;
                float yr = cr[i][j] + DxP[(size_t)row*2*N + col];
                float yi = ci[i][j] + DxP[(size_t)row*2*N + N + col];
                float outr = yr*yr + yr;
                float outi = yr*yi + yi;
                size_t p = ((size_t)row*N + col)*2;
                hOut[p]   = resid[p]   + 0.1f*outr;
                hOut[p+1] = resid[p+1] + 0.1f*outi;
            }
        }
    }
}

// ---------------- real GEMM + bias + sigmoid (gates) --------------------------
// A: [M, K] row-major (g_xn, K=2D=512), W: [K,N], out: [M,N]
__global__ void __launch_bounds__(256, 2)
rgemm_sig_kernel(const float* __restrict__ A, int lda,
                 const float* __restrict__ W,
                 const float* __restrict__ bias,
                 int K, int N, float* __restrict__ out)
{
    __shared__ float As[16][64], Bs[16][64];
    int tid = threadIdx.x;
    int m0 = blockIdx.y * 64, n0 = blockIdx.x * 64;
    int arow = tid >> 2,  ac = (tid & 3) * 4;
    int brow = tid >> 4,  bc = (tid & 15) * 4;
    int ty = tid >> 4,    tx = tid & 15;

    float acc[4][4] = {};
    for (int k0 = 0; k0 < K; k0 += 16) {
        float4 va = *(const float4*)(A + (size_t)(m0+arow)*lda + k0 + ac);
        As[ac+0][arow]=va.x; As[ac+1][arow]=va.y; As[ac+2][arow]=va.z; As[ac+3][arow]=va.w;
        *(float4*)&Bs[brow][bc] = *(const float4*)(W + (size_t)(k0+brow)*N + n0 + bc);
        __syncthreads();
        #pragma unroll
        for (int kk = 0; kk < 16; kk++) {
            float4 a4 = *(float4*)&As[kk][ty*4];
            float4 b4 = *(float4*)&Bs[kk][tx*4];
            float aa[4]={a4.x,a4.y,a4.z,a4.w};
            float bb[4]={b4.x,b4.y,b4.z,b4.w};
            #pragma unroll
            for (int i=0;i<4;i++)
                #pragma unroll
                for (int j=0;j<4;j++)
                    acc[i][j] = fmaf(aa[i], bb[j], acc[i][j]);
        }
        __syncthreads();
    }
    #pragma unroll
    for (int i=0;i<4;i++) {
        int row = m0 + ty*4 + i;
        #pragma unroll
        for (int j=0;j<4;j++) {
            int col = n0 + tx*4 + j;
            float v = acc[i][j] + bias[col];
            out[(size_t)row*N + col] = 1.0f / (1.0f + expf(-v));
        }
    }
}

// ---------------- diagonal sequential scan -------------------------------------
// One thread per (b, sd). h_new = g*Bx + (1-g)*damping*R(theta)*h
__global__ void scan_kernel(int layer,
                            const float* __restrict__ h0,
                            const float* __restrict__ theta,
                            const float* __restrict__ damp_p,
                            float* __restrict__ hfin_out)
{
    int t = blockIdx.x * blockDim.x + threadIdx.x;   // 0..2047
    int b = t / SDc, sd = t % SDc;
    float th = theta [layer*SDc + sd];
    float dp = damp_p[layer*SDc + sd];
    float damp = 0.5f + 0.5f / (1.0f + expf(-dp));
    float cd = cosf(th) * damp;
    float sn = sinf(th) * damp;

    size_t hidx = ((size_t)(layer*Bc + b)*SDc + sd) * 2;
    float hr = h0[hidx], hi = h0[hidx+1];

    const float* __restrict__ bx = g_Bx;
    const float* __restrict__ gt = g_gt;
    float* __restrict__ ha = g_hall;

    #pragma unroll 4
    for (int s = 0; s < Sc; s++) {
        size_t base = (size_t)b*Sc + s;
        float gv  = gt[base*SDc + sd];
        float bxr = bx[base*2*SDc + sd];
        float bxi = bx[base*2*SDc + SDc + sd];
        float tr = hr*cd - hi*sn;
        float ti = hr*sn + hi*cd;
        float og = 1.0f - gv;
        hr = fmaf(gv, bxr, og*tr);
        hi = fmaf(gv, bxi, og*ti);
        ha[base*2*SDc + sd]       = hr;
        ha[base*2*SDc + SDc + sd] = hi;
    }
    hfin_out[hidx]   = hr;
    hfin_out[hidx+1] = hi;
}

// ---------------- host ----------------------------------------------------------
extern "C" void kernel_launch(void* const* d_in, const int* in_sizes, int n_in,
                              void* d_out, int out_size)
{
    const float* x      = (const float*)d_in[0];
    const float* h0     = (const float*)d_in[1];
    const float* theta  = (const float*)d_in[2];
    const float* damp_p = (const float*)d_in[3];
    const float* BWr    = (const float*)d_in[4];
    const float* BWi    = (const float*)d_in[5];
    const float* CWr    = (const float*)d_in[6];
    const float* CWi    = (const float*)d_in[7];
    const float* DWr    = (const float*)d_in[8];
    const float* DWi    = (const float*)d_in[9];
    const float* gW     = (const float*)d_in[10];
    const float* gb     = (const float*)d_in[11];
    const float* ng     = (const float*)d_in[12];
    const float* nb     = (const float*)d_in[13];
    const float* og     = (const float*)d_in[14];
    const float* ob     = (const float*)d_in[15];
    float* out = (float*)d_out;

    float *hbuf, *xn, *bx, *gts, *hall, *dx;
    cudaGetSymbolAddress((void**)&hbuf, g_h);
    cudaGetSymbolAddress((void**)&xn,   g_xn);
    cudaGetSymbolAddress((void**)&bx,   g_Bx);
    cudaGetSymbolAddress((void**)&gts,  g_gt);
    cudaGetSymbolAddress((void**)&hall, g_hall);
    cudaGetSymbolAddress((void**)&dx,   g_Dx);

    float* hfin = out + (size_t)Mc*Dc*2;   // new_hidden region after main output

    for (int l = 0; l < Lc; l++) {
        const float* src = (l == 0) ? x : hbuf;   // residual / LN input

        // 1. LayerNorm -> planes (also serves as gate_in)
        ln_kernel<<<Mc, 256>>>(src, ng + l*Dc, nb + l*Dc, xn, nullptr);

        // 2. Bx = clin(xn, BWr, BWi)   [M,2D] x [D,SD] complex
        {
            dim3 g(SDc/64, Mc/64);
            cgemm_kernel<<<g, 256>>>(xn, 2*Dc,
                                     BWr + (size_t)l*Dc*SDc, BWi + (size_t)l*Dc*SDc,
                                     Dc, SDc, bx, nullptr, nullptr, nullptr);
        }
        // 3. gates = sigmoid(xn2d @ gW + gb)    [M,512] x [512,512]
        {
            dim3 g(SDc/64, Mc/64);
            rgemm_sig_kernel<<<g, 256>>>(xn, 2*Dc,
                                         gW + (size_t)l*2*Dc*SDc, gb + (size_t)l*SDc,
                                         2*Dc, SDc, gts);
        }
        // 4. Dx = clin(xn, DWr, DWi)   [M,2D] x [D,D] complex
        {
            dim3 g(Dc/64, Mc/64);
            cgemm_kernel<<<g, 256>>>(xn, 2*Dc,
                                     DWr + (size_t)l*Dc*Dc, DWi + (size_t)l*Dc*Dc,
                                     Dc, Dc, dx, nullptr, nullptr, nullptr);
        }
        // 5. sequential diagonal scan -> g_hall, h_fin
        scan_kernel<<<16, 128>>>(l, h0, theta, damp_p, hfin);

        // 6. y = clin(h_all, CWr, CWi) + Dx; out = yr*y + y; h = resid + 0.1*out
        {
            dim3 g(Dc/64, Mc/64);
            cgemm_kernel<<<g, 256>>>(hall, 2*SDc,
                                     CWr + (size_t)l*SDc*Dc, CWi + (size_t)l*SDc*Dc,
                                     SDc, Dc, nullptr, dx, src, hbuf);
        }
    }

    // final LayerNorm -> interleaved output
    ln_kernel<<<Mc, 256>>>(hbuf, og, ob, nullptr, out);
}

// round 3
// speedup vs baseline: 4.3793x; 4.3793x over previous
#include <cuda_runtime.h>
#include <cuda_bf16.h>
#include <math.h>
#include <cstdint>

#define Lc   8
#define Bc   4
#define Sc   2048
#define Dc   256
#define SDc  512
#define Mc   (Bc*Sc)      // 8192

#define K1   1536         // 3 * 512 (xn hi/hi/lo split)
#define N1   1536         // 1024 (Bx interleaved) + 512 (gate)
#define K2   4608         // 3*1024 (hall split) + 3*512 (xn split)
#define N2   512          // interleaved y pairs
#define NCH  32
#define CHLEN 64

// ----------------------------- device scratch --------------------------------
__device__ __nv_bfloat16 g_A1[(size_t)Mc*K1];
__device__ __nv_bfloat16 g_A2[(size_t)Mc*K2];
__device__ __nv_bfloat16 g_W1[(size_t)Lc*N1*K1];   // [l][n][k]
__device__ __nv_bfloat16 g_W2[(size_t)Lc*N2*K2];   // [l][n][k]
__device__ float g_Bx[(size_t)Mc*1024];            // interleaved (bxr,bxi)
__device__ float g_gt[(size_t)Mc*512];
__device__ float g_h [(size_t)Mc*512];             // interleaved activation
__device__ float g_carry[(size_t)NCH*Bc*SDc*4];
__device__ float g_hst  [(size_t)NCH*Bc*SDc*2];

// ----------------------------- helpers ----------------------------------------
__device__ __forceinline__ uint32_t s2u(const void* p){
    uint32_t a;
    asm("{ .reg .u64 t; cvta.to.shared.u64 t, %1; cvt.u32.u64 %0, t; }" : "=r"(a) : "l"(p));
    return a;
}
__device__ __forceinline__ void cpa16(uint32_t s, const void* g){
    asm volatile("cp.async.cg.shared.global [%0], [%1], 16;" :: "r"(s), "l"(g));
}
__device__ __forceinline__ uint32_t swz(uint32_t o){ return o ^ ((o >> 3) & 0x70); }

__device__ __forceinline__ void ldsm4(uint32_t* r, uint32_t addr){
    asm volatile("ldmatrix.sync.aligned.m8n8.x4.shared.b16 {%0,%1,%2,%3}, [%4];"
        : "=r"(r[0]), "=r"(r[1]), "=r"(r[2]), "=r"(r[3]) : "r"(addr));
}
__device__ __forceinline__ void mma16816(float* d, const uint32_t* a, const uint32_t* b){
    asm volatile("mma.sync.aligned.m16n8k16.row.col.f32.bf16.bf16.f32 "
        "{%0,%1,%2,%3}, {%4,%5,%6,%7}, {%8,%9}, {%0,%1,%2,%3};"
        : "+f"(d[0]), "+f"(d[1]), "+f"(d[2]), "+f"(d[3])
        : "r"(a[0]), "r"(a[1]), "r"(a[2]), "r"(a[3]), "r"(b[0]), "r"(b[1]));
}

// ----------------------------- weight prep ------------------------------------
__global__ void prep_w1(const float* __restrict__ BWr, const float* __restrict__ BWi,
                        const float* __restrict__ gW)
{
    size_t i = (size_t)blockIdx.x * blockDim.x + threadIdx.x;
    if (i >= (size_t)Lc*N1*K1) return;
    int k = (int)(i % K1); size_t r = i / K1; int n = (int)(r % N1); int l = (int)(r / N1);
    int blk = k / 512, kk = k % 512;
    float v;
    if (n < 1024) {
        int j = n >> 1, p = n & 1;
        if (kk < 256) v = p ? BWi[((size_t)l*256+kk)*512+j] : BWr[((size_t)l*256+kk)*512+j];
        else { int kr = kk-256; v = p ? BWr[((size_t)l*256+kr)*512+j] : -BWi[((size_t)l*256+kr)*512+j]; }
    } else {
        v = gW[((size_t)l*512+kk)*512 + (n-1024)];
    }
    __nv_bfloat16 hi = __float2bfloat16(v);
    g_W1[i] = (blk == 1) ? __float2bfloat16(v - __bfloat162float(hi)) : hi;
}

__global__ void prep_w2(const float* __restrict__ CWr, const float* __restrict__ CWi,
                        const float* __restrict__ DWr, const float* __restrict__ DWi)
{
    size_t i = (size_t)blockIdx.x * blockDim.x + threadIdx.x;
    if (i >= (size_t)Lc*N2*K2) return;
    int k = (int)(i % K2); size_t r = i / K2; int n = (int)(r % N2); int l = (int)(r / N2);
    int j = n >> 1, p = n & 1;
    float v; int blk;
    if (k < 3072) {
        blk = k / 1024; int kk = k % 1024;
        if (kk < 512) v = p ? CWi[((size_t)l*512+kk)*256+j] : CWr[((size_t)l*512+kk)*256+j];
        else { int ki = kk-512; v = p ? CWr[((size_t)l*512+ki)*256+j] : -CWi[((size_t)l*512+ki)*256+j]; }
    } else {
        int k2 = k - 3072; blk = k2 / 512; int kk = k2 % 512;
        if (kk < 256) v = p ? DWi[((size_t)l*256+kk)*256+j] : DWr[((size_t)l*256+kk)*256+j];
        else { int kr = kk-256; v = p ? DWr[((size_t)l*256+kr)*256+j] : -DWi[((size_t)l*256+kr)*256+j]; }
    }
    __nv_bfloat16 hi = __float2bfloat16(v);
    g_W2[i] = (blk == 1) ? __float2bfloat16(v - __bfloat162float(hi)) : hi;
}

// ----------------------------- LayerNorm ---------------------------------------
__global__ void ln_kernel(const float* __restrict__ src,
                          const float* __restrict__ gw, const float* __restrict__ bw,
                          int final_mode, float* __restrict__ outInter)
{
    int m = blockIdx.x;
    int d = threadIdx.x;
    const float* row = src + (size_t)m * Dc * 2;
    float hr = row[2*d], hi = row[2*d+1];

    float v0 = hr, v1 = hi, v2 = hr*hr, v3 = hi*hi;
    #pragma unroll
    for (int o = 16; o > 0; o >>= 1) {
        v0 += __shfl_down_sync(0xffffffffu, v0, o);
        v1 += __shfl_down_sync(0xffffffffu, v1, o);
        v2 += __shfl_down_sync(0xffffffffu, v2, o);
        v3 += __shfl_down_sync(0xffffffffu, v3, o);
    }
    __shared__ float sm[4][8];
    __shared__ float stats[4];
    int w = d >> 5, ln = d & 31;
    if (ln == 0) { sm[0][w]=v0; sm[1][w]=v1; sm[2][w]=v2; sm[3][w]=v3; }
    __syncthreads();
    if (d == 0) {
        float s0=0,s1=0,s2=0,s3=0;
        #pragma unroll
        for (int i=0;i<8;i++){ s0+=sm[0][i]; s1+=sm[1][i]; s2+=sm[2][i]; s3+=sm[3][i]; }
        float inv = 1.0f / (float)Dc;
        float mur = s0*inv, mui = s1*inv;
        stats[0]=mur; stats[1]=rsqrtf(s2*inv - mur*mur + 1e-5f);
        stats[2]=mui; stats[3]=rsqrtf(s3*inv - mui*mui + 1e-5f);
    }
    __syncthreads();
    float nr = (hr - stats[0]) * stats[1] * gw[d] + bw[d];
    float ni = (hi - stats[2]) * stats[3] * gw[d] + bw[d];

    if (final_mode) {
        float* o = outInter + (size_t)m*Dc*2;
        o[2*d] = nr; o[2*d+1] = ni;
    } else {
        __nv_bfloat16 rh = __float2bfloat16(nr);
        __nv_bfloat16 rl = __float2bfloat16(nr - __bfloat162float(rh));
        __nv_bfloat16 ih = __float2bfloat16(ni);
        __nv_bfloat16 il = __float2bfloat16(ni - __bfloat162float(ih));
        __nv_bfloat16* a1 = g_A1 + (size_t)m*K1;
        a1[d]=rh; a1[256+d]=ih; a1[512+d]=rh; a1[768+d]=ih; a1[1024+d]=rl; a1[1280+d]=il;
        __nv_bfloat16* a2 = g_A2 + (size_t)m*K2 + 3072;
        a2[d]=rh; a2[256+d]=ih; a2[512+d]=rh; a2[768+d]=ih; a2[1024+d]=rl; a2[1280+d]=il;
    }
}

// ----------------------------- scan (chunked) ----------------------------------
__global__ void scan1(int layer, const float* __restrict__ theta, const float* __restrict__ damp)
{
    int t = blockIdx.x*blockDim.x + threadIdx.x;   // 65536
    int sd = t & 511, ch = (t >> 9) & 31, b = t >> 14;
    float th = theta[layer*SDc+sd], dp = damp[layer*SDc+sd];
    float dm = 0.5f + 0.5f/(1.f+expf(-dp));
    float cd = cosf(th)*dm, sn = sinf(th)*dm;
    float Ar=1.f, Ai=0.f, Br=0.f, Bi=0.f;
    int base_row = b*Sc + ch*CHLEN;
    for (int s=0;s<CHLEN;s++){
        int row = base_row + s;
        float g = g_gt[(size_t)row*512+sd];
        float2 bx = *(const float2*)&g_Bx[(size_t)row*1024 + 2*sd];
        float og = 1.f - g;
        float ar = og*cd, ai = og*sn;
        float nAr = ar*Ar - ai*Ai, nAi = ar*Ai + ai*Ar;
        float nBr = ar*Br - ai*Bi + g*bx.x;
        float nBi = ar*Bi + ai*Br + g*bx.y;
        Ar=nAr; Ai=nAi; Br=nBr; Bi=nBi;
    }
    size_t o = ((size_t)ch*Bc*SDc + (size_t)b*SDc + sd)*4;
    float4 cc; cc.x=Ar; cc.y=Ai; cc.z=Br; cc.w=Bi;
    *(float4*)&g_carry[o] = cc;
}

__global__ void scan2(int layer, const float* __restrict__ h0, float* __restrict__ hfin)
{
    int t = blockIdx.x*blockDim.x + threadIdx.x;
    if (t >= Bc*SDc) return;
    int b = t / SDc, sd = t % SDc;
    size_t hidx = ((size_t)(layer*Bc+b)*SDc + sd)*2;
    float hr = h0[hidx], hi = h0[hidx+1];
    for (int ch = 0; ch < NCH; ch++){
        size_t o = (size_t)ch*Bc*SDc + t;
        g_hst[o*2] = hr; g_hst[o*2+1] = hi;
        float4 cc = *(const float4*)&g_carry[o*4];
        float nr = cc.x*hr - cc.y*hi + cc.z;
        float ni = cc.x*hi + cc.y*hr + cc.w;
        hr = nr; hi = ni;
    }
    hfin[hidx] = hr; hfin[hidx+1] = hi;
}

__global__ void scan3(int layer, const float* __restrict__ theta, const float* __restrict__ damp)
{
    int t = blockIdx.x*blockDim.x + threadIdx.x;
    int sd = t & 511, ch = (t >> 9) & 31, b = t >> 14;
    float th = theta[layer*SDc+sd], dp = damp[layer*SDc+sd];
    float dm = 0.5f + 0.5f/(1.f+expf(-dp));
    float cd = cosf(th)*dm, sn = sinf(th)*dm;
    size_t o = (size_t)ch*Bc*SDc + (size_t)b*SDc + sd;
    float hr = g_hst[o*2], hi = g_hst[o*2+1];
    int base_row = b*Sc + ch*CHLEN;
    for (int s=0;s<CHLEN;s++){
        int row = base_row + s;
        float g = g_gt[(size_t)row*512+sd];
        float2 bx = *(const float2*)&g_Bx[(size_t)row*1024 + 2*sd];
        float tr = hr*cd - hi*sn, ti = hr*sn + hi*cd;
        float og = 1.f - g;
        hr = fmaf(g, bx.x, og*tr);
        hi = fmaf(g, bx.y, og*ti);
        __nv_bfloat16 hh = __float2bfloat16(hr);
        __nv_bfloat16 hl = __float2bfloat16(hr - __bfloat162float(hh));
        __nv_bfloat16 ih = __float2bfloat16(hi);
        __nv_bfloat16 il = __float2bfloat16(hi - __bfloat162float(ih));
        __nv_bfloat16* a2 = g_A2 + (size_t)row*K2;
        a2[sd]=hh; a2[512+sd]=ih; a2[1024+sd]=hh; a2[1536+sd]=ih; a2[2048+sd]=hl; a2[2560+sd]=il;
    }
}

// ----------------------------- HMMA GEMM ---------------------------------------
// D[m][n] = sum_k A[m][k] * W[n][k]; 128x128 tile, BK=64, 3-stage cp.async.
// mode 0: n<1024 -> oBx; n>=1024 -> oGt = sigmoid(v + gb)
// mode 1: pairs (2j,2j+1)=(yr,yi): hOut = resid + 0.1*(yr*y + y)
#define ST 3
#define STAGE_BYTES 32768          // A 16KB + B 16KB
#define GEMM_SMEM (ST*STAGE_BYTES)

__global__ void __launch_bounds__(256, 1)
mma_gemm(const __nv_bfloat16* __restrict__ A, const __nv_bfloat16* __restrict__ W,
         int K, int mode,
         float* __restrict__ oBx, float* __restrict__ oGt, const float* __restrict__ gb,
         const float* __restrict__ resid, float* __restrict__ hOut)
{
    extern __shared__ char smem[];
    uint32_t sb = s2u(smem);
    int tid = threadIdx.x, wid = tid >> 5, L = tid & 31;
    int m0 = blockIdx.y * 128, n0 = blockIdx.x * 128;
    const int NK = K >> 6;

    // ---- cp.async mapping: 8 x 16B chunks per thread per stage ----
    const __nv_bfloat16* gbaseA = A + (size_t)m0 * K;
    const __nv_bfloat16* gbaseB = W + (size_t)n0 * K;
    uint32_t soff[8]; uint32_t goff[8]; uint32_t isB[8];
    #pragma unroll
    for (int i = 0; i < 8; i++) {
        int q = tid + i*256;          // 0..2047
        isB[i] = (uint32_t)(q >> 10);
        int qq = q & 1023;
        int r = qq >> 3, c = qq & 7;
        goff[i] = (uint32_t)(r * K + c * 8);
        soff[i] = (isB[i] ? 16384u : 0u) + swz((uint32_t)(r*128 + c*16));
    }

    // ---- ldmatrix lane addressing (SW128: swz = row*128 + (chunk^(row&7))*16) ----
    int wm = wid >> 2, wn = wid & 3;
    int rowA0 = wm*64 + (L & 7) + ((L >> 3) & 1) * 8;
    uint32_t aBase = (uint32_t)rowA0 * 128; uint32_t aS = (uint32_t)(rowA0 & 7);
    uint32_t aC = (uint32_t)(L >> 4);
    int rowB0 = wn*32 + (L & 7) + ((L >> 4) & 1) * 8;
    uint32_t bBase = 16384u + (uint32_t)rowB0 * 128; uint32_t bS = (uint32_t)(rowB0 & 7);
    uint32_t bC = (uint32_t)((L >> 3) & 1);

    float c[4][4][4];
    #pragma unroll
    for (int i=0;i<4;i++)
        #pragma unroll
        for (int j=0;j<4;j++)
            #pragma unroll
            for (int e=0;e<4;e++) c[i][j][e] = 0.f;

    // ---- prologue: load stages 0,1 ----
    #pragma unroll
    for (int s = 0; s < ST-1; s++) {
        if (s < NK) {
            uint32_t st = sb + s*STAGE_BYTES;
            uint32_t kb = (uint32_t)(s * 64);
            #pragma unroll
            for (int i = 0; i < 8; i++) {
                const __nv_bfloat16* g = (isB[i] ? gbaseB : gbaseA) + goff[i] + kb;
                cpa16(st + soff[i], g);
            }
        }
        asm volatile("cp.async.commit_group;" ::: "memory");
    }

    for (int ki = 0; ki < NK; ki++) {
        asm volatile("cp.async.wait_group %0;" :: "n"(ST-2) : "memory");
        __syncthreads();

        uint32_t st = sb + (uint32_t)(ki % ST) * STAGE_BYTES;
        #pragma unroll
        for (int kk = 0; kk < 4; kk++) {
            uint32_t a[4][4], b[2][4];
            uint32_t ca = (uint32_t)(kk*2);
            #pragma unroll
            for (int mt = 0; mt < 4; mt++)
                ldsm4(a[mt], st + aBase + (uint32_t)mt*2048 + (((ca + aC) ^ aS) << 4));
            #pragma unroll
            for (int bt = 0; bt < 2; bt++)
                ldsm4(b[bt], st + bBase + (uint32_t)bt*2048 + (((ca + bC) ^ bS) << 4));
            #pragma unroll
            for (int mt = 0; mt < 4; mt++)
                #pragma unroll
                for (int nt = 0; nt < 4; nt++)
                    mma16816(c[mt][nt], a[mt], &b[nt>>1][(nt&1)*2]);
        }

        // load stage ki+ST-1 (overwrites stage computed at ki-1; safe after sync)
        int ls = ki + ST - 1;
        if (ls < NK) {
            uint32_t st2 = sb + (uint32_t)(ls % ST) * STAGE_BYTES;
            uint32_t kb = (uint32_t)(ls * 64);
            #pragma unroll
            for (int i = 0; i < 8; i++) {
                const __nv_bfloat16* g = (isB[i] ? gbaseB : gbaseA) + goff[i] + kb;
                cpa16(st2 + soff[i], g);
            }
        }
        asm volatile("cp.async.commit_group;" ::: "memory");
    }

    // ---- epilogue: direct float2 stores ----
    int lrow = L >> 2, lcol = (L & 3) * 2;
    int mRow = m0 + wm*64 + lrow;
    int nCol = n0 + wn*32 + lcol;
    #pragma unroll
    for (int mt = 0; mt < 4; mt++) {
        #pragma unroll
        for (int nt = 0; nt < 4; nt++) {
            int row = mRow + mt*16;
            int col = nCol + nt*8;
            float* cc = c[mt][nt];
            if (mode == 0) {
                if (col < 1024) {
                    float2 v0; v0.x = cc[0]; v0.y = cc[1];
                    float2 v1; v1.x = cc[2]; v1.y = cc[3];
                    *(float2*)&oBx[(size_t)row*1024 + col] = v0;
                    *(float2*)&oBx[(size_t)(row+8)*1024 + col] = v1;
                } else {
                    int gc = col - 1024;
                    float b0 = gb[gc], b1 = gb[gc+1];
                    float2 v0, v1;
                    v0.x = 1.f/(1.f+expf(-(cc[0]+b0)));
                    v0.y = 1.f/(1.f+expf(-(cc[1]+b1)));
                    v1.x = 1.f/(1.f+expf(-(cc[2]+b0)));
                    v1.y = 1.f/(1.f+expf(-(cc[3]+b1)));
                    *(float2*)&oGt[(size_t)row*512 + gc] = v0;
                    *(float2*)&oGt[(size_t)(row+8)*512 + gc] = v1;
                }
            } else {
                float2 r0 = *(const float2*)&resid[(size_t)row*512 + col];
                float2 r1 = *(const float2*)&resid[(size_t)(row+8)*512 + col];
                float2 v0, v1;
                v0.x = r0.x + 0.1f*(cc[0]*cc[0] + cc[0]);
                v0.y = r0.y + 0.1f*(cc[0]*cc[1] + cc[1]);
                v1.x = r1.x + 0.1f*(cc[2]*cc[2] + cc[2]);
                v1.y = r1.y + 0.1f*(cc[2]*cc[3] + cc[3]);
                *(float2*)&hOut[(size_t)row*512 + col] = v0;
                *(float2*)&hOut[(size_t)(row+8)*512 + col] = v1;
            }
        }
    }
}

// ----------------------------- host ---------------------------------------------
extern "C" void kernel_launch(void* const* d_in, const int* in_sizes, int n_in,
                              void* d_out, int out_size)
{
    const float* x      = (const float*)d_in[0];
    const float* h0     = (const float*)d_in[1];
    const float* theta  = (const float*)d_in[2];
    const float* damp_p = (const float*)d_in[3];
    const float* BWr    = (const float*)d_in[4];
    const float* BWi    = (const float*)d_in[5];
    const float* CWr    = (const float*)d_in[6];
    const float* CWi    = (const float*)d_in[7];
    const float* DWr    = (const float*)d_in[8];
    const float* DWi    = (const float*)d_in[9];
    const float* gW     = (const float*)d_in[10];
    const float* gb     = (const float*)d_in[11];
    const float* ng     = (const float*)d_in[12];
    const float* nb     = (const float*)d_in[13];
    const float* og     = (const float*)d_in[14];
    const float* ob     = (const float*)d_in[15];
    float* out = (float*)d_out;

    cudaFuncSetAttribute(mma_gemm, cudaFuncAttributeMaxDynamicSharedMemorySize, GEMM_SMEM);

    __nv_bfloat16 *a1, *a2, *w1, *w2;
    float *bx, *gt, *hbuf;
    cudaGetSymbolAddress((void**)&a1, g_A1);
    cudaGetSymbolAddress((void**)&a2, g_A2);
    cudaGetSymbolAddress((void**)&w1, g_W1);
    cudaGetSymbolAddress((void**)&w2, g_W2);
    cudaGetSymbolAddress((void**)&bx, g_Bx);
    cudaGetSymbolAddress((void**)&gt, g_gt);
    cudaGetSymbolAddress((void**)&hbuf, g_h);

    float* hfin = out + (size_t)Mc*Dc*2;

    {
        size_t n1 = (size_t)Lc*N1*K1;
        prep_w1<<<(unsigned)((n1+255)/256), 256>>>(BWr, BWi, gW);
        size_t n2 = (size_t)Lc*N2*K2;
        prep_w2<<<(unsigned)((n2+255)/256), 256>>>(CWr, CWi, DWr, DWi);
    }

    for (int l = 0; l < Lc; l++) {
        const float* src = (l == 0) ? x : hbuf;

        ln_kernel<<<Mc, 256>>>(src, ng + l*Dc, nb + l*Dc, 0, nullptr);

        // GEMM1: Bx + gates
        {
            dim3 g(N1/128, Mc/128);
            mma_gemm<<<g, 256, GEMM_SMEM>>>(a1, w1 + (size_t)l*N1*K1, K1, 0,
                                            bx, gt, gb + (size_t)l*SDc, nullptr, nullptr);
        }

        scan1<<<256, 256>>>(l, theta, damp_p);
        scan2<<<8, 256>>>(l, h0, hfin);
        scan3<<<256, 256>>>(l, theta, damp_p);

        // GEMM2: y = C*hall + D*xn; nonlinearity + residual fused
        {
            dim3 g(N2/128, Mc/128);
            mma_gemm<<<g, 256, GEMM_SMEM>>>(a2, w2 + (size_t)l*N2*K2, K2, 1,
                                            nullptr, nullptr, nullptr, src, hbuf);
        }
    }

    ln_kernel<<<Mc, 256>>>(hbuf, og, ob, 1, out);
}